// round 15
// baseline (speedup 1.0000x reference)
#include <cuda_runtime.h>
#include <cuda_bf16.h>
#include <cuda_fp16.h>
#include <cstdint>

#define BATCH 32
#define DIMC  512
#define HEADS 8
#define HD    64
#define NPIX  1024
#define SCALE 0.125f
#define LOG2E 1.44269504f

// ---------------------------------------------------------------------------
// scratch (module-load allocated)
// ---------------------------------------------------------------------------
__device__ __align__(16) __half g_w16 [(size_t)3*DIMC*DIMC];          // fp16 W
__device__ __align__(16) __half g_xhi [(size_t)BATCH*NPIX*DIMC];      // [b][n][c] fp16 hi
__device__ __align__(16) __half g_xlo [(size_t)BATCH*NPIX*DIMC];      // fp16 lo
__device__ __align__(16) __half g_q16h[(size_t)BATCH*HEADS*NPIX*HD];  // [b,p,n,d]
__device__ __align__(16) __half g_q16l[(size_t)BATCH*HEADS*NPIX*HD];
__device__ __align__(16) __half g_k16 [(size_t)BATCH*HEADS*NPIX*HD];  // [b,p,n,d]
__device__ __align__(16) __half g_v16 [(size_t)BATCH*HEADS*HD*NPIX];  // [b,p,d,n]

// ---------------------------------------------------------------------------
// helpers
// ---------------------------------------------------------------------------
__device__ __forceinline__ uint32_t smem_u32(const void* p) {
    uint32_t a;
    asm("{ .reg .u64 t; cvta.to.shared.u64 t, %1; cvt.u32.u64 %0, t; }" : "=r"(a) : "l"(p));
    return a;
}
__device__ __forceinline__ uint32_t packh2(float a, float b) {
    __half2 h = __floats2half2_rn(a, b);
    return reinterpret_cast<uint32_t&>(h);
}
__device__ __forceinline__ void split2h(float a, float b, uint32_t& hi, uint32_t& lo) {
    __half2 h = __floats2half2_rn(a, b);
    hi = reinterpret_cast<uint32_t&>(h);
    float ra = a - __low2float(h);
    float rb = b - __high2float(h);
    __half2 l = __floats2half2_rn(ra, rb);
    lo = reinterpret_cast<uint32_t&>(l);
}
__device__ __forceinline__ float ex2(float x) {
    float y;
    asm("ex2.approx.ftz.f32 %0, %1;" : "=f"(y) : "f"(x));
    return y;
}
__device__ __forceinline__ void mma_f16(float* c, const uint32_t* a, const uint32_t* b) {
    asm volatile(
        "mma.sync.aligned.m16n8k16.row.col.f32.f16.f16.f32 "
        "{%0,%1,%2,%3},{%4,%5,%6,%7},{%8,%9},{%0,%1,%2,%3};"
        : "+f"(c[0]), "+f"(c[1]), "+f"(c[2]), "+f"(c[3])
        : "r"(a[0]), "r"(a[1]), "r"(a[2]), "r"(a[3]), "r"(b[0]), "r"(b[1]));
}
__device__ __forceinline__ void ldsm4(uint32_t* r, uint32_t addr) {
    asm volatile("ldmatrix.sync.aligned.m8n8.x4.shared.b16 {%0,%1,%2,%3}, [%4];"
        : "=r"(r[0]), "=r"(r[1]), "=r"(r[2]), "=r"(r[3]) : "r"(addr));
}
#define CP_ASYNC16(dst, src) \
    asm volatile("cp.async.cg.shared.global [%0], [%1], 16;" :: "r"(dst), "l"(src))
#define CP_COMMIT() asm volatile("cp.async.commit_group;" ::: "memory")
#define CP_WAIT0()  asm volatile("cp.async.wait_group 0;" ::: "memory")

// ---------------------------------------------------------------------------
// prep kernels
// ---------------------------------------------------------------------------
__global__ void prep_w_kernel(const float* __restrict__ w)
{
    int i = blockIdx.x * blockDim.x + threadIdx.x;
    int total = 3 * DIMC * DIMC;
    for (; i < total; i += gridDim.x * blockDim.x)
        g_w16[i] = __float2half_rn(w[i]);
}

// transpose X [b,c,n] -> [b,n,c], fp16 hi/lo, packed 4B stores
__global__ __launch_bounds__(256) void prep_x_kernel(const float* __restrict__ x)
{
    __shared__ float ts[32][33];
    const int b  = blockIdx.z;
    const int c0 = blockIdx.y * 32;
    const int n0 = blockIdx.x * 32;
    const int t  = threadIdx.x;
    const int tx = t & 31;
    const int ty = t >> 5;

    const float* xb = x + (size_t)b * DIMC * NPIX;
    #pragma unroll
    for (int k = 0; k < 4; k++)
        ts[ty + k * 8][tx] = xb[(size_t)(c0 + ty + k * 8) * NPIX + n0 + tx];
    __syncthreads();

    const int cp = (t & 15) * 2;
    #pragma unroll
    for (int kk = 0; kk < 2; kk++) {
        int nl = (t >> 4) + kk * 16;
        float v0 = ts[cp][nl];
        float v1 = ts[cp + 1][nl];
        uint32_t uhi, ulo;
        split2h(v0, v1, uhi, ulo);
        size_t idx = ((size_t)b * NPIX + n0 + nl) * DIMC + c0 + cp;
        *(uint32_t*)&g_xhi[idx] = uhi;
        *(uint32_t*)&g_xlo[idx] = ulo;
    }
}

// ---------------------------------------------------------------------------
// QKV projection v3 (fp16 2-pass): C = W16 * (Xhi + Xlo).
// cp.async 2-stage, one barrier/K-step. BM=128 BN=128 BK=32, 2 CTAs/SM.
// Stage 30720 B: W[128*80] Xhi[128*80] Xlo[128*80].
// Epilogue emits q (fp16 hi/lo, scaled), k (+rel, fp16), v (fp16, [d][n]).
// ---------------------------------------------------------------------------
#define QKV_STAGE 30720
__global__ __launch_bounds__(256, 2) void qkv_mma(
    const float* __restrict__ bias, const float* __restrict__ hrel,
    const float* __restrict__ wrel)
{
    extern __shared__ __align__(16) char smem[];
    const uint32_t sbase = smem_u32(smem);

    const int t = threadIdx.x, lane = t & 31, wid = t >> 5;
    const int wm = wid & 3, wn = wid >> 2;
    const int r  = lane >> 2, kq = (lane & 3) * 2;
    const int grp = lane >> 3, lrow = lane & 7;
    const int otile = blockIdx.x * 128, ntile = blockIdx.y * 128, b = blockIdx.z;

    const uint32_t offA = (uint32_t)(((grp & 1) * 8 + lrow) * 80 + (grp >> 1) * 16);
    const uint32_t offB = (uint32_t)(((grp >> 1) * 8 + lrow) * 80 + (grp & 1) * 16);

    const __half* Aw  = g_w16 + (size_t)otile * DIMC;
    const __half* Bhi = g_xhi + ((size_t)b * NPIX + ntile) * DIMC;
    const __half* Blo = g_xlo + ((size_t)b * NPIX + ntile) * DIMC;

    auto issue = [&](int kc, int s) {
        const uint32_t sb = sbase + s * QKV_STAGE;
        #pragma unroll
        for (int it = 0; it < 2; it++) {
            int i = t + it * 256;
            int row = i >> 2, cp = i & 3;
            uint32_t d = (uint32_t)(row * 80 + cp * 16);
            size_t go = (size_t)row * DIMC + kc + cp * 8;
            CP_ASYNC16(sb + d,          (const char*)(Aw  + go));
            CP_ASYNC16(sb + 10240 + d,  (const char*)(Bhi + go));
            CP_ASYNC16(sb + 20480 + d,  (const char*)(Blo + go));
        }
        CP_COMMIT();
    };

    issue(0, 0);

    float acc[2][8][4] = {};

    for (int i = 0; i < 16; i++) {
        CP_WAIT0();
        __syncthreads();
        if (i < 15) issue((i + 1) * 32, (i + 1) & 1);

        const uint32_t uA  = sbase + (i & 1) * QKV_STAGE;
        const uint32_t uBh = uA + 10240;
        const uint32_t uBl = uA + 20480;

        #pragma unroll
        for (int ks = 0; ks < 2; ks++) {
            uint32_t aw[2][4], bh[8][2], bl[8][2];
            #pragma unroll
            for (int mt = 0; mt < 2; mt++) {
                uint32_t ra = offA + (uint32_t)((wm * 32 + mt * 16) * 80 + ks * 32);
                ldsm4(aw[mt], uA + ra);
            }
            #pragma unroll
            for (int ntp = 0; ntp < 4; ntp++) {
                uint32_t rb = offB + (uint32_t)((wn * 64 + ntp * 16) * 80 + ks * 32);
                uint32_t th[4], tl[4];
                ldsm4(th, uBh + rb);
                ldsm4(tl, uBl + rb);
                bh[2*ntp][0] = th[0]; bh[2*ntp][1] = th[1];
                bh[2*ntp+1][0] = th[2]; bh[2*ntp+1][1] = th[3];
                bl[2*ntp][0] = tl[0]; bl[2*ntp][1] = tl[1];
                bl[2*ntp+1][0] = tl[2]; bl[2*ntp+1][1] = tl[3];
            }
            #pragma unroll
            for (int mt = 0; mt < 2; mt++)
                #pragma unroll
                for (int nt = 0; nt < 8; nt++) {
                    mma_f16(acc[mt][nt], aw[mt], bh[nt]);
                    mma_f16(acc[mt][nt], aw[mt], bl[nt]);
                }
        }
    }
    __syncthreads();

    // epilogue
    float* st = (float*)smem;
    const int sec = blockIdx.x >> 2;
    const int p0  = (blockIdx.x & 3) * 2;
    const int bp0 = b * HEADS;

    for (int h = 0; h < 2; h++) {
        if (wn == h) {
            #pragma unroll
            for (int mt = 0; mt < 2; mt++)
                #pragma unroll
                for (int nt = 0; nt < 8; nt++) {
                    int row = wm * 32 + mt * 16 + r;
                    int c   = nt * 8 + kq;
                    st[row * 65 + c]           = acc[mt][nt][0];
                    st[row * 65 + c + 1]       = acc[mt][nt][1];
                    st[(row + 8) * 65 + c]     = acc[mt][nt][2];
                    st[(row + 8) * 65 + c + 1] = acc[mt][nt][3];
                }
        }
        __syncthreads();

        int nbase = ntile + h * 64;
        if (sec < 2) {
            int nl = t >> 2, quad = t & 3;
            int head = quad >> 1, dseg = (quad & 1) * 32;
            int p = p0 + head;
            int n = nbase + nl;
            size_t base = ((size_t)(bp0 + p) * NPIX + n) * HD;
            const float* hr = hrel + (size_t)(n >> 5) * DIMC + p * HD;
            const float* wr = wrel + (size_t)(n & 31) * DIMC + p * HD;
            #pragma unroll
            for (int j = 0; j < 16; j++) {
                int d = dseg + 2 * j;
                int m = head * 64 + d;
                float v0 = st[m * 65 + nl] + bias[otile + m];
                float v1 = st[(m + 1) * 65 + nl] + bias[otile + m + 1];
                if (sec == 0) {
                    v0 *= SCALE * LOG2E; v1 *= SCALE * LOG2E;
                    uint32_t uhi, ulo;
                    split2h(v0, v1, uhi, ulo);
                    *(uint32_t*)&g_q16h[base + d] = uhi;
                    *(uint32_t*)&g_q16l[base + d] = ulo;
                } else {
                    v0 += hr[d] + wr[d]; v1 += hr[d + 1] + wr[d + 1];
                    *(uint32_t*)&g_k16[base + d] = packh2(v0, v1);
                }
            }
        } else {
            int m = t >> 1, seg = (t & 1) * 32;
            int head = m >> 6, d = m & 63, p = p0 + head;
            float bi = bias[otile + m];
            size_t base = ((size_t)(bp0 + p) * HD + d) * NPIX + nbase + seg;
            #pragma unroll
            for (int j = 0; j < 16; j++) {
                int n0 = seg + 2 * j;
                float v0 = st[m * 65 + n0] + bi;
                float v1 = st[m * 65 + n0 + 1] + bi;
                *(uint32_t*)&g_v16[base + 2 * j] = packh2(v0, v1);
            }
        }
        __syncthreads();
    }
}

// ---------------------------------------------------------------------------
// Flash attention (R14-proven): fp16 operands, S 2-pass (q hi/lo), PV 2-pass
// (P hi/lo), no-max softmax with -8 bias. 128 thr, BM=128, BN=32, 2-stage.
// Stage 9728 B: K[32*144] V[64*80].
// ---------------------------------------------------------------------------
#define ATTN_STAGE 9728
__global__ __launch_bounds__(128, 2) void attn_mma(float* __restrict__ out)
{
    extern __shared__ __align__(16) char smem[];
    const uint32_t sbase = smem_u32(smem);

    const int t = threadIdx.x, lane = t & 31, wid = t >> 5;
    const int r = lane >> 2, kq = (lane & 3) * 2;
    const int grp = lane >> 3, lrow = lane & 7;
    const int bp = blockIdx.y, qtile = blockIdx.x * 128;

    const uint32_t offK = (uint32_t)(((grp >> 1) * 8 + lrow) * 144 + (grp & 1) * 16);
    const uint32_t offV = (uint32_t)(((grp >> 1) * 8 + lrow) * 80  + (grp & 1) * 16);

    const __half* Kg = g_k16 + (size_t)bp * NPIX * HD;
    const __half* Vg = g_v16 + (size_t)bp * HD * NPIX;

    auto issue_tile = [&](int kt0, int s) {
        const uint32_t sb = sbase + s * ATTN_STAGE;
        #pragma unroll
        for (int it = 0; it < 2; it++) {
            int i = t + it * 128;
            int row = i >> 3, cp = i & 7;
            uint32_t d = (uint32_t)(row * 144 + cp * 16);
            CP_ASYNC16(sb + d, (const char*)(Kg + (size_t)(kt0 + row) * HD + cp * 8));
        }
        #pragma unroll
        for (int it = 0; it < 2; it++) {
            int i = t + it * 128;
            int row = i >> 2, cp = i & 3;
            uint32_t d = (uint32_t)(row * 80 + cp * 16);
            CP_ASYNC16(sb + 4608 + d, (const char*)(Vg + (size_t)row * NPIX + kt0 + cp * 8));
        }
        CP_COMMIT();
    };

    issue_tile(0, 0);

    // Q fragments (fp16 hi/lo): warp owns rows [qtile + wid*32, +32)
    uint32_t qh[2][4][4], ql[2][4][4];
    {
        const uint32_t* Qh = (const uint32_t*)(g_q16h + ((size_t)bp * NPIX + qtile + wid * 32) * HD);
        const uint32_t* Ql = (const uint32_t*)(g_q16l + ((size_t)bp * NPIX + qtile + wid * 32) * HD);
        #pragma unroll
        for (int mt = 0; mt < 2; mt++)
            #pragma unroll
            for (int dk = 0; dk < 4; dk++) {
                int dw = dk * 8 + (lane & 3);
                int i0 = (mt * 16 + r) * 32 + dw, i1 = i0 + 8 * 32;
                qh[mt][dk][0] = Qh[i0]; qh[mt][dk][1] = Qh[i1];
                qh[mt][dk][2] = Qh[i0 + 4]; qh[mt][dk][3] = Qh[i1 + 4];
                ql[mt][dk][0] = Ql[i0]; ql[mt][dk][1] = Ql[i1];
                ql[mt][dk][2] = Ql[i0 + 4]; ql[mt][dk][3] = Ql[i1 + 4];
            }
    }

    float lsum[2][2] = {};
    float o[2][8][4] = {};

    for (int c = 0; c < 32; c++) {
        CP_WAIT0();
        __syncthreads();
        if (c < 31) issue_tile((c + 1) * 32, (c + 1) & 1);

        const uint32_t sK = sbase + (c & 1) * ATTN_STAGE;
        const uint32_t sV = sK + 4608;

        // S = Q K'^T, 2-pass fp16, accumulator pre-biased by -8
        float s[2][4][4];
        #pragma unroll
        for (int mt = 0; mt < 2; mt++)
            #pragma unroll
            for (int nt = 0; nt < 4; nt++)
                #pragma unroll
                for (int j = 0; j < 4; j++)
                    s[mt][nt][j] = -8.0f;

        #pragma unroll
        for (int dk = 0; dk < 4; dk++) {
            #pragma unroll
            for (int ntp = 0; ntp < 2; ntp++) {
                uint32_t a = sK + offK + (uint32_t)(ntp * 2304 + dk * 32);
                uint32_t h[4];
                ldsm4(h, a);
                #pragma unroll
                for (int mt = 0; mt < 2; mt++) {
                    mma_f16(s[mt][2*ntp],   qh[mt][dk], h);
                    mma_f16(s[mt][2*ntp+1], qh[mt][dk], h + 2);
                }
                #pragma unroll
                for (int mt = 0; mt < 2; mt++) {
                    mma_f16(s[mt][2*ntp],   ql[mt][dk], h);
                    mma_f16(s[mt][2*ntp+1], ql[mt][dk], h + 2);
                }
            }
        }

        // P = 2^s, exact fp32 l, P -> fp16 hi/lo
        uint32_t ph[2][2][4], pl[2][2][4];
        #pragma unroll
        for (int mt = 0; mt < 2; mt++)
            #pragma unroll
            for (int j = 0; j < 2; j++) {
                float e0 = ex2(s[mt][2*j][0]);
                float e1 = ex2(s[mt][2*j][1]);
                float e2 = ex2(s[mt][2*j][2]);
                float e3 = ex2(s[mt][2*j][3]);
                float e4 = ex2(s[mt][2*j+1][0]);
                float e5 = ex2(s[mt][2*j+1][1]);
                float e6 = ex2(s[mt][2*j+1][2]);
                float e7 = ex2(s[mt][2*j+1][3]);
                lsum[mt][0] += (e0 + e1) + (e4 + e5);
                lsum[mt][1] += (e2 + e3) + (e6 + e7);
                split2h(e0, e1, ph[mt][j][0], pl[mt][j][0]);
                split2h(e2, e3, ph[mt][j][1], pl[mt][j][1]);
                split2h(e4, e5, ph[mt][j][2], pl[mt][j][2]);
                split2h(e6, e7, ph[mt][j][3], pl[mt][j][3]);
            }

        // O += P V, 2-pass fp16
        #pragma unroll
        for (int kk = 0; kk < 2; kk++) {
            #pragma unroll
            for (int ntp = 0; ntp < 4; ntp++) {
                uint32_t a = sV + offV + (uint32_t)(ntp * 1280 + kk * 32);
                uint32_t h[4];
                ldsm4(h, a);
                #pragma unroll
                for (int mt = 0; mt < 2; mt++) {
                    mma_f16(o[mt][2*ntp],   ph[mt][kk], h);
                    mma_f16(o[mt][2*ntp+1], ph[mt][kk], h + 2);
                }
                #pragma unroll
                for (int mt = 0; mt < 2; mt++) {
                    mma_f16(o[mt][2*ntp],   pl[mt][kk], h);
                    mma_f16(o[mt][2*ntp+1], pl[mt][kk], h + 2);
                }
            }
        }
    }

    // deferred l reduction
    #pragma unroll
    for (int mt = 0; mt < 2; mt++)
        #pragma unroll
        for (int i = 0; i < 2; i++) {
            lsum[mt][i] += __shfl_xor_sync(0xffffffffu, lsum[mt][i], 1);
            lsum[mt][i] += __shfl_xor_sync(0xffffffffu, lsum[mt][i], 2);
        }

    __syncthreads();
    // finalize + transposed store: st[64 d][132]
    float* st = (float*)smem;
    #pragma unroll
    for (int mt = 0; mt < 2; mt++) {
        float inv0 = 1.f / lsum[mt][0], inv1 = 1.f / lsum[mt][1];
        int row = wid * 32 + mt * 16 + r;
        #pragma unroll
        for (int nt = 0; nt < 8; nt++) {
            int d0 = nt * 8 + kq;
            st[d0 * 132 + row]           = o[mt][nt][0] * inv0;
            st[(d0 + 1) * 132 + row]     = o[mt][nt][1] * inv0;
            st[d0 * 132 + row + 8]       = o[mt][nt][2] * inv1;
            st[(d0 + 1) * 132 + row + 8] = o[mt][nt][3] * inv1;
        }
    }
    __syncthreads();

    const int b = bp >> 3, p = bp & 7;
    float* og = out + ((size_t)b * DIMC + p * HD) * NPIX + qtile;
    int d = t >> 1, seg = (t & 1) * 64;
    #pragma unroll
    for (int j = 0; j < 64; j++)
        og[(size_t)d * NPIX + seg + j] = st[d * 132 + seg + j];
}

extern "C" void kernel_launch(void* const* d_in, const int* in_sizes, int n_in,
                              void* d_out, int out_size)
{
    const float* x    = (const float*)d_in[0];
    const float* w    = (const float*)d_in[1];
    const float* bias = (const float*)d_in[2];
    const float* hrel = (const float*)d_in[3];
    const float* wrel = (const float*)d_in[4];
    float* out = (float*)d_out;

    cudaFuncSetAttribute(qkv_mma, cudaFuncAttributeMaxDynamicSharedMemorySize,
                         2 * QKV_STAGE);
    cudaFuncSetAttribute(attn_mma, cudaFuncAttributeMaxDynamicSharedMemorySize, 33792);

    prep_w_kernel<<<192, 256>>>(w);
    dim3 gx(NPIX / 32, DIMC / 32, BATCH);
    prep_x_kernel<<<gx, 256>>>(x);

    dim3 g1(12, 8, BATCH);
    qkv_mma<<<g1, 256, 2 * QKV_STAGE>>>(bias, hrel, wrel);

    dim3 g2(8, 256);
    attn_mma<<<g2, 128, 33792>>>(out);
}

// round 16
// speedup vs baseline: 1.5361x; 1.5361x over previous
#include <cuda_runtime.h>
#include <cuda_bf16.h>
#include <cuda_fp16.h>
#include <cstdint>

#define BATCH 32
#define DIMC  512
#define HEADS 8
#define HD    64
#define NPIX  1024
#define SCALE 0.125f
#define LOG2E 1.44269504f

// ---------------------------------------------------------------------------
// scratch (module-load allocated)
// ---------------------------------------------------------------------------
__device__ __align__(16) __half g_w16 [(size_t)3*DIMC*DIMC];          // fp16 W
__device__ __align__(16) __half g_xhi [(size_t)BATCH*NPIX*DIMC];      // [b][n][c] fp16 hi
__device__ __align__(16) __half g_xlo [(size_t)BATCH*NPIX*DIMC];      // fp16 lo
__device__ __align__(16) __half g_q16h[(size_t)BATCH*HEADS*NPIX*HD];  // [b,p,n,d]
__device__ __align__(16) __half g_q16l[(size_t)BATCH*HEADS*NPIX*HD];
__device__ __align__(16) __half g_k16 [(size_t)BATCH*HEADS*NPIX*HD];  // [b,p,n,d]
__device__ __align__(16) __half g_v16 [(size_t)BATCH*HEADS*HD*NPIX];  // [b,p,d,n]

// ---------------------------------------------------------------------------
// helpers
// ---------------------------------------------------------------------------
__device__ __forceinline__ uint32_t smem_u32(const void* p) {
    uint32_t a;
    asm("{ .reg .u64 t; cvta.to.shared.u64 t, %1; cvt.u32.u64 %0, t; }" : "=r"(a) : "l"(p));
    return a;
}
__device__ __forceinline__ uint32_t packh2(float a, float b) {
    __half2 h = __floats2half2_rn(a, b);
    return reinterpret_cast<uint32_t&>(h);
}
__device__ __forceinline__ void split2h(float a, float b, uint32_t& hi, uint32_t& lo) {
    __half2 h = __floats2half2_rn(a, b);
    hi = reinterpret_cast<uint32_t&>(h);
    float ra = a - __low2float(h);
    float rb = b - __high2float(h);
    __half2 l = __floats2half2_rn(ra, rb);
    lo = reinterpret_cast<uint32_t&>(l);
}
__device__ __forceinline__ float ex2(float x) {
    float y;
    asm("ex2.approx.ftz.f32 %0, %1;" : "=f"(y) : "f"(x));
    return y;
}
__device__ __forceinline__ void mma_f16(float* c, const uint32_t* a, const uint32_t* b) {
    asm volatile(
        "mma.sync.aligned.m16n8k16.row.col.f32.f16.f16.f32 "
        "{%0,%1,%2,%3},{%4,%5,%6,%7},{%8,%9},{%0,%1,%2,%3};"
        : "+f"(c[0]), "+f"(c[1]), "+f"(c[2]), "+f"(c[3])
        : "r"(a[0]), "r"(a[1]), "r"(a[2]), "r"(a[3]), "r"(b[0]), "r"(b[1]));
}
__device__ __forceinline__ void ldsm4(uint32_t* r, uint32_t addr) {
    asm volatile("ldmatrix.sync.aligned.m8n8.x4.shared.b16 {%0,%1,%2,%3}, [%4];"
        : "=r"(r[0]), "=r"(r[1]), "=r"(r[2]), "=r"(r[3]) : "r"(addr));
}
#define CP_ASYNC16(dst, src) \
    asm volatile("cp.async.cg.shared.global [%0], [%1], 16;" :: "r"(dst), "l"(src))
#define CP_COMMIT() asm volatile("cp.async.commit_group;" ::: "memory")
#define CP_WAIT0()  asm volatile("cp.async.wait_group 0;" ::: "memory")

// ---------------------------------------------------------------------------
// prep kernels
// ---------------------------------------------------------------------------
__global__ void prep_w_kernel(const float* __restrict__ w)
{
    int i = blockIdx.x * blockDim.x + threadIdx.x;
    int total = 3 * DIMC * DIMC;
    for (; i < total; i += gridDim.x * blockDim.x)
        g_w16[i] = __float2half_rn(w[i]);
}

// transpose X [b,c,n] -> [b,n,c], fp16 hi/lo, packed 4B stores
__global__ __launch_bounds__(256) void prep_x_kernel(const float* __restrict__ x)
{
    __shared__ float ts[32][33];
    const int b  = blockIdx.z;
    const int c0 = blockIdx.y * 32;
    const int n0 = blockIdx.x * 32;
    const int t  = threadIdx.x;
    const int tx = t & 31;
    const int ty = t >> 5;

    const float* xb = x + (size_t)b * DIMC * NPIX;
    #pragma unroll
    for (int k = 0; k < 4; k++)
        ts[ty + k * 8][tx] = xb[(size_t)(c0 + ty + k * 8) * NPIX + n0 + tx];
    __syncthreads();

    const int cp = (t & 15) * 2;
    #pragma unroll
    for (int kk = 0; kk < 2; kk++) {
        int nl = (t >> 4) + kk * 16;
        float v0 = ts[cp][nl];
        float v1 = ts[cp + 1][nl];
        uint32_t uhi, ulo;
        split2h(v0, v1, uhi, ulo);
        size_t idx = ((size_t)b * NPIX + n0 + nl) * DIMC + c0 + cp;
        *(uint32_t*)&g_xhi[idx] = uhi;
        *(uint32_t*)&g_xlo[idx] = ulo;
    }
}

// ---------------------------------------------------------------------------
// QKV projection (fp16 2-pass): C = W16 * (Xhi + Xlo).
// cp.async 2-stage, one barrier/K-step. BM=128 BN=128 BK=32, 2 CTAs/SM.
// Stage 30720 B: W[128*80] Xhi[128*80] Xlo[128*80].
// ---------------------------------------------------------------------------
#define QKV_STAGE 30720
__global__ __launch_bounds__(256, 2) void qkv_mma(
    const float* __restrict__ bias, const float* __restrict__ hrel,
    const float* __restrict__ wrel)
{
    extern __shared__ __align__(16) char smem[];
    const uint32_t sbase = smem_u32(smem);

    const int t = threadIdx.x, lane = t & 31, wid = t >> 5;
    const int wm = wid & 3, wn = wid >> 2;
    const int r  = lane >> 2, kq = (lane & 3) * 2;
    const int grp = lane >> 3, lrow = lane & 7;
    const int otile = blockIdx.x * 128, ntile = blockIdx.y * 128, b = blockIdx.z;

    const uint32_t offA = (uint32_t)(((grp & 1) * 8 + lrow) * 80 + (grp >> 1) * 16);
    const uint32_t offB = (uint32_t)(((grp >> 1) * 8 + lrow) * 80 + (grp & 1) * 16);

    const __half* Aw  = g_w16 + (size_t)otile * DIMC;
    const __half* Bhi = g_xhi + ((size_t)b * NPIX + ntile) * DIMC;
    const __half* Blo = g_xlo + ((size_t)b * NPIX + ntile) * DIMC;

    auto issue = [&](int kc, int s) {
        const uint32_t sb = sbase + s * QKV_STAGE;
        #pragma unroll
        for (int it = 0; it < 2; it++) {
            int i = t + it * 256;
            int row = i >> 2, cp = i & 3;
            uint32_t d = (uint32_t)(row * 80 + cp * 16);
            size_t go = (size_t)row * DIMC + kc + cp * 8;
            CP_ASYNC16(sb + d,          (const char*)(Aw  + go));
            CP_ASYNC16(sb + 10240 + d,  (const char*)(Bhi + go));
            CP_ASYNC16(sb + 20480 + d,  (const char*)(Blo + go));
        }
        CP_COMMIT();
    };

    issue(0, 0);

    float acc[2][8][4] = {};

    for (int i = 0; i < 16; i++) {
        CP_WAIT0();
        __syncthreads();
        if (i < 15) issue((i + 1) * 32, (i + 1) & 1);

        const uint32_t uA  = sbase + (i & 1) * QKV_STAGE;
        const uint32_t uBh = uA + 10240;
        const uint32_t uBl = uA + 20480;

        #pragma unroll
        for (int ks = 0; ks < 2; ks++) {
            uint32_t aw[2][4], bh[8][2], bl[8][2];
            #pragma unroll
            for (int mt = 0; mt < 2; mt++) {
                uint32_t ra = offA + (uint32_t)((wm * 32 + mt * 16) * 80 + ks * 32);
                ldsm4(aw[mt], uA + ra);
            }
            #pragma unroll
            for (int ntp = 0; ntp < 4; ntp++) {
                uint32_t rb = offB + (uint32_t)((wn * 64 + ntp * 16) * 80 + ks * 32);
                uint32_t th[4], tl[4];
                ldsm4(th, uBh + rb);
                ldsm4(tl, uBl + rb);
                bh[2*ntp][0] = th[0]; bh[2*ntp][1] = th[1];
                bh[2*ntp+1][0] = th[2]; bh[2*ntp+1][1] = th[3];
                bl[2*ntp][0] = tl[0]; bl[2*ntp][1] = tl[1];
                bl[2*ntp+1][0] = tl[2]; bl[2*ntp+1][1] = tl[3];
            }
            #pragma unroll
            for (int mt = 0; mt < 2; mt++)
                #pragma unroll
                for (int nt = 0; nt < 8; nt++) {
                    mma_f16(acc[mt][nt], aw[mt], bh[nt]);
                    mma_f16(acc[mt][nt], aw[mt], bl[nt]);
                }
        }
    }
    __syncthreads();

    // epilogue
    float* st = (float*)smem;
    const int sec = blockIdx.x >> 2;
    const int p0  = (blockIdx.x & 3) * 2;
    const int bp0 = b * HEADS;

    for (int h = 0; h < 2; h++) {
        if (wn == h) {
            #pragma unroll
            for (int mt = 0; mt < 2; mt++)
                #pragma unroll
                for (int nt = 0; nt < 8; nt++) {
                    int row = wm * 32 + mt * 16 + r;
                    int c   = nt * 8 + kq;
                    st[row * 65 + c]           = acc[mt][nt][0];
                    st[row * 65 + c + 1]       = acc[mt][nt][1];
                    st[(row + 8) * 65 + c]     = acc[mt][nt][2];
                    st[(row + 8) * 65 + c + 1] = acc[mt][nt][3];
                }
        }
        __syncthreads();

        int nbase = ntile + h * 64;
        if (sec < 2) {
            int nl = t >> 2, quad = t & 3;
            int head = quad >> 1, dseg = (quad & 1) * 32;
            int p = p0 + head;
            int n = nbase + nl;
            size_t base = ((size_t)(bp0 + p) * NPIX + n) * HD;
            const float* hr = hrel + (size_t)(n >> 5) * DIMC + p * HD;
            const float* wr = wrel + (size_t)(n & 31) * DIMC + p * HD;
            #pragma unroll
            for (int j = 0; j < 16; j++) {
                int d = dseg + 2 * j;
                int m = head * 64 + d;
                float v0 = st[m * 65 + nl] + bias[otile + m];
                float v1 = st[(m + 1) * 65 + nl] + bias[otile + m + 1];
                if (sec == 0) {
                    v0 *= SCALE * LOG2E; v1 *= SCALE * LOG2E;
                    uint32_t uhi, ulo;
                    split2h(v0, v1, uhi, ulo);
                    *(uint32_t*)&g_q16h[base + d] = uhi;
                    *(uint32_t*)&g_q16l[base + d] = ulo;
                } else {
                    v0 += hr[d] + wr[d]; v1 += hr[d + 1] + wr[d + 1];
                    *(uint32_t*)&g_k16[base + d] = packh2(v0, v1);
                }
            }
        } else {
            int m = t >> 1, seg = (t & 1) * 32;
            int head = m >> 6, d = m & 63, p = p0 + head;
            float bi = bias[otile + m];
            size_t base = ((size_t)(bp0 + p) * HD + d) * NPIX + nbase + seg;
            #pragma unroll
            for (int j = 0; j < 16; j++) {
                int n0 = seg + 2 * j;
                float v0 = st[m * 65 + n0] + bi;
                float v1 = st[m * 65 + n0 + 1] + bi;
                *(uint32_t*)&g_v16[base + 2 * j] = packh2(v0, v1);
            }
        }
        __syncthreads();
    }
}

// ---------------------------------------------------------------------------
// Flash attention (R14-proven): fp16 operands, S 2-pass (q hi/lo), PV 2-pass
// (P hi/lo), no-max softmax with -8 bias. 128 thr, BM=128, BN=32, 2-stage.
// Stage 9728 B: K[32*144] V[64*80].
// ---------------------------------------------------------------------------
#define ATTN_STAGE 9728
__global__ __launch_bounds__(128, 2) void attn_mma(float* __restrict__ out)
{
    extern __shared__ __align__(16) char smem[];
    const uint32_t sbase = smem_u32(smem);

    const int t = threadIdx.x, lane = t & 31, wid = t >> 5;
    const int r = lane >> 2, kq = (lane & 3) * 2;
    const int grp = lane >> 3, lrow = lane & 7;
    const int bp = blockIdx.y, qtile = blockIdx.x * 128;

    const uint32_t offK = (uint32_t)(((grp >> 1) * 8 + lrow) * 144 + (grp & 1) * 16);
    const uint32_t offV = (uint32_t)(((grp >> 1) * 8 + lrow) * 80  + (grp & 1) * 16);

    const __half* Kg = g_k16 + (size_t)bp * NPIX * HD;
    const __half* Vg = g_v16 + (size_t)bp * HD * NPIX;

    auto issue_tile = [&](int kt0, int s) {
        const uint32_t sb = sbase + s * ATTN_STAGE;
        #pragma unroll
        for (int it = 0; it < 2; it++) {
            int i = t + it * 128;
            int row = i >> 3, cp = i & 7;
            uint32_t d = (uint32_t)(row * 144 + cp * 16);
            CP_ASYNC16(sb + d, (const char*)(Kg + (size_t)(kt0 + row) * HD + cp * 8));
        }
        #pragma unroll
        for (int it = 0; it < 2; it++) {
            int i = t + it * 128;
            int row = i >> 2, cp = i & 3;
            uint32_t d = (uint32_t)(row * 80 + cp * 16);
            CP_ASYNC16(sb + 4608 + d, (const char*)(Vg + (size_t)row * NPIX + kt0 + cp * 8));
        }
        CP_COMMIT();
    };

    issue_tile(0, 0);

    // Q fragments (fp16 hi/lo): warp owns rows [qtile + wid*32, +32)
    uint32_t qh[2][4][4], ql[2][4][4];
    {
        const uint32_t* Qh = (const uint32_t*)(g_q16h + ((size_t)bp * NPIX + qtile + wid * 32) * HD);
        const uint32_t* Ql = (const uint32_t*)(g_q16l + ((size_t)bp * NPIX + qtile + wid * 32) * HD);
        #pragma unroll
        for (int mt = 0; mt < 2; mt++)
            #pragma unroll
            for (int dk = 0; dk < 4; dk++) {
                int dw = dk * 8 + (lane & 3);
                int i0 = (mt * 16 + r) * 32 + dw, i1 = i0 + 8 * 32;
                qh[mt][dk][0] = Qh[i0]; qh[mt][dk][1] = Qh[i1];
                qh[mt][dk][2] = Qh[i0 + 4]; qh[mt][dk][3] = Qh[i1 + 4];
                ql[mt][dk][0] = Ql[i0]; ql[mt][dk][1] = Ql[i1];
                ql[mt][dk][2] = Ql[i0 + 4]; ql[mt][dk][3] = Ql[i1 + 4];
            }
    }

    float lsum[2][2] = {};
    float o[2][8][4] = {};

    for (int c = 0; c < 32; c++) {
        CP_WAIT0();
        __syncthreads();
        if (c < 31) issue_tile((c + 1) * 32, (c + 1) & 1);

        const uint32_t sK = sbase + (c & 1) * ATTN_STAGE;
        const uint32_t sV = sK + 4608;

        // S = Q K'^T, 2-pass fp16, accumulator pre-biased by -8
        float s[2][4][4];
        #pragma unroll
        for (int mt = 0; mt < 2; mt++)
            #pragma unroll
            for (int nt = 0; nt < 4; nt++)
                #pragma unroll
                for (int j = 0; j < 4; j++)
                    s[mt][nt][j] = -8.0f;

        #pragma unroll
        for (int dk = 0; dk < 4; dk++) {
            #pragma unroll
            for (int ntp = 0; ntp < 2; ntp++) {
                uint32_t a = sK + offK + (uint32_t)(ntp * 2304 + dk * 32);
                uint32_t h[4];
                ldsm4(h, a);
                #pragma unroll
                for (int mt = 0; mt < 2; mt++) {
                    mma_f16(s[mt][2*ntp],   qh[mt][dk], h);
                    mma_f16(s[mt][2*ntp+1], qh[mt][dk], h + 2);
                }
                #pragma unroll
                for (int mt = 0; mt < 2; mt++) {
                    mma_f16(s[mt][2*ntp],   ql[mt][dk], h);
                    mma_f16(s[mt][2*ntp+1], ql[mt][dk], h + 2);
                }
            }
        }

        // P = 2^s, exact fp32 l, P -> fp16 hi/lo
        uint32_t ph[2][2][4], pl[2][2][4];
        #pragma unroll
        for (int mt = 0; mt < 2; mt++)
            #pragma unroll
            for (int j = 0; j < 2; j++) {
                float e0 = ex2(s[mt][2*j][0]);
                float e1 = ex2(s[mt][2*j][1]);
                float e2 = ex2(s[mt][2*j][2]);
                float e3 = ex2(s[mt][2*j][3]);
                float e4 = ex2(s[mt][2*j+1][0]);
                float e5 = ex2(s[mt][2*j+1][1]);
                float e6 = ex2(s[mt][2*j+1][2]);
                float e7 = ex2(s[mt][2*j+1][3]);
                lsum[mt][0] += (e0 + e1) + (e4 + e5);
                lsum[mt][1] += (e2 + e3) + (e6 + e7);
                split2h(e0, e1, ph[mt][j][0], pl[mt][j][0]);
                split2h(e2, e3, ph[mt][j][1], pl[mt][j][1]);
                split2h(e4, e5, ph[mt][j][2], pl[mt][j][2]);
                split2h(e6, e7, ph[mt][j][3], pl[mt][j][3]);
            }

        // O += P V, 2-pass fp16
        #pragma unroll
        for (int kk = 0; kk < 2; kk++) {
            #pragma unroll
            for (int ntp = 0; ntp < 4; ntp++) {
                uint32_t a = sV + offV + (uint32_t)(ntp * 1280 + kk * 32);
                uint32_t h[4];
                ldsm4(h, a);
                #pragma unroll
                for (int mt = 0; mt < 2; mt++) {
                    mma_f16(o[mt][2*ntp],   ph[mt][kk], h);
                    mma_f16(o[mt][2*ntp+1], ph[mt][kk], h + 2);
                }
                #pragma unroll
                for (int mt = 0; mt < 2; mt++) {
                    mma_f16(o[mt][2*ntp],   pl[mt][kk], h);
                    mma_f16(o[mt][2*ntp+1], pl[mt][kk], h + 2);
                }
            }
        }
    }

    // deferred l reduction
    #pragma unroll
    for (int mt = 0; mt < 2; mt++)
        #pragma unroll
        for (int i = 0; i < 2; i++) {
            lsum[mt][i] += __shfl_xor_sync(0xffffffffu, lsum[mt][i], 1);
            lsum[mt][i] += __shfl_xor_sync(0xffffffffu, lsum[mt][i], 2);
        }

    __syncthreads();
    // finalize + transposed store: st[64 d][132]
    float* st = (float*)smem;
    #pragma unroll
    for (int mt = 0; mt < 2; mt++) {
        float inv0 = 1.f / lsum[mt][0], inv1 = 1.f / lsum[mt][1];
        int row = wid * 32 + mt * 16 + r;
        #pragma unroll
        for (int nt = 0; nt < 8; nt++) {
            int d0 = nt * 8 + kq;
            st[d0 * 132 + row]           = o[mt][nt][0] * inv0;
            st[(d0 + 1) * 132 + row]     = o[mt][nt][1] * inv0;
            st[d0 * 132 + row + 8]       = o[mt][nt][2] * inv1;
            st[(d0 + 1) * 132 + row + 8] = o[mt][nt][3] * inv1;
        }
    }
    __syncthreads();

    const int b = bp >> 3, p = bp & 7;
    float* og = out + ((size_t)b * DIMC + p * HD) * NPIX + qtile;
    int d = t >> 1, seg = (t & 1) * 64;
    #pragma unroll
    for (int j = 0; j < 64; j++)
        og[(size_t)d * NPIX + seg + j] = st[d * 132 + seg + j];
}

extern "C" void kernel_launch(void* const* d_in, const int* in_sizes, int n_in,
                              void* d_out, int out_size)
{
    const float* x    = (const float*)d_in[0];
    const float* w    = (const float*)d_in[1];
    const float* bias = (const float*)d_in[2];
    const float* hrel = (const float*)d_in[3];
    const float* wrel = (const float*)d_in[4];
    float* out = (float*)d_out;

    cudaFuncSetAttribute(qkv_mma, cudaFuncAttributeMaxDynamicSharedMemorySize,
                         2 * QKV_STAGE);
    cudaFuncSetAttribute(attn_mma, cudaFuncAttributeMaxDynamicSharedMemorySize, 33792);

    prep_w_kernel<<<192, 256>>>(w);
    dim3 gx(NPIX / 32, DIMC / 32, BATCH);
    prep_x_kernel<<<gx, 256>>>(x);

    dim3 g1(12, 8, BATCH);
    qkv_mma<<<g1, 256, 2 * QKV_STAGE>>>(bias, hrel, wrel);

    dim3 g2(8, 256);
    attn_mma<<<g2, 128, 33792>>>(out);
}